// round 5
// baseline (speedup 1.0000x reference)
#include <cuda_runtime.h>

#define N_ROWS 8192
#define D_DIM  1024
#define THREADS 256
#define NBLOCKS 1024
#define WARPS_PER_BLOCK (THREADS / 32)                   // 8
#define F4_PER_LANE (D_DIM / 4 / 32)                     // 8
#define PARTIALS_PER_THREAD (NBLOCKS / THREADS)          // 4

__device__ float        g_partial[NBLOCKS];
__device__ unsigned int g_count = 0;

__global__ __launch_bounds__(THREADS, 8)   // 32 regs exactly -> 8 CTAs/SM = 64 warps, single wave
void fused_cosine_mse_kernel(const float* __restrict__ A,
                             const float* __restrict__ B,
                             const float* __restrict__ labels,
                             float* __restrict__ out) {
    const int t   = threadIdx.x;
    const int wid = t >> 5;
    const int lid = t & 31;
    const int row = blockIdx.x * WARPS_PER_BLOCK + wid;   // one row per warp

    const float4* a4 = reinterpret_cast<const float4*>(A + (size_t)row * D_DIM) + lid;
    const float4* b4 = reinterpret_cast<const float4*>(B + (size_t)row * D_DIM) + lid;

    const float label = labels[row];   // overlap with main stream

    // Depth-2 software pipeline: keep 4 independent LDG.128 in flight
    float4 a0 = __ldcs(a4);
    float4 b0 = __ldcs(b4);
    float4 a1 = __ldcs(a4 + 32);
    float4 b1 = __ldcs(b4 + 32);

    float dot = 0.0f, na = 0.0f, nb = 0.0f;
    float dot2 = 0.0f, na2 = 0.0f, nb2 = 0.0f;

    #pragma unroll
    for (int k = 0; k < F4_PER_LANE; k += 2) {
        float4 an0, bn0, an1, bn1;
        if (k + 2 < F4_PER_LANE) {
            an0 = __ldcs(a4 + (k + 2) * 32);
            bn0 = __ldcs(b4 + (k + 2) * 32);
            an1 = __ldcs(a4 + (k + 3) * 32);
            bn1 = __ldcs(b4 + (k + 3) * 32);
        }
        dot  += a0.x * b0.x + a0.y * b0.y + a0.z * b0.z + a0.w * b0.w;
        na   += a0.x * a0.x + a0.y * a0.y + a0.z * a0.z + a0.w * a0.w;
        nb   += b0.x * b0.x + b0.y * b0.y + b0.z * b0.z + b0.w * b0.w;
        dot2 += a1.x * b1.x + a1.y * b1.y + a1.z * b1.z + a1.w * b1.w;
        na2  += a1.x * a1.x + a1.y * a1.y + a1.z * a1.z + a1.w * a1.w;
        nb2  += b1.x * b1.x + b1.y * b1.y + b1.z * b1.z + b1.w * b1.w;
        a0 = an0; b0 = bn0; a1 = an1; b1 = bn1;
    }
    dot += dot2; na += na2; nb += nb2;

    // Butterfly reduce: every lane ends with full-row sums
    #pragma unroll
    for (int off = 16; off > 0; off >>= 1) {
        dot += __shfl_xor_sync(0xFFFFFFFFu, dot, off);
        na  += __shfl_xor_sync(0xFFFFFFFFu, na,  off);
        nb  += __shfl_xor_sync(0xFFFFFFFFu, nb,  off);
    }

    const float score = dot * rsqrtf(na * nb);
    const float diff  = score - label;
    const float acc   = diff * diff;

    // Block reduction of 8 warp values
    __shared__ float s_warp[WARPS_PER_BLOCK];
    __shared__ bool  s_is_last;
    if (lid == 0) s_warp[wid] = acc;
    __syncthreads();

    if (t == 0) {
        float bsum = 0.0f;
        #pragma unroll
        for (int w = 0; w < WARPS_PER_BLOCK; w++) bsum += s_warp[w];
        g_partial[blockIdx.x] = bsum;
        __threadfence();
        const unsigned int prev = atomicAdd(&g_count, 1u);
        s_is_last = (prev == NBLOCKS - 1);
    }
    __syncthreads();

    if (s_is_last) {
        __threadfence();   // acquire: all g_partial writes visible
        float v = 0.0f;
        #pragma unroll
        for (int i = 0; i < PARTIALS_PER_THREAD; i++)
            v += g_partial[t + i * THREADS];

        #pragma unroll
        for (int off = 16; off > 0; off >>= 1)
            v += __shfl_xor_sync(0xFFFFFFFFu, v, off);

        __shared__ float s_final[WARPS_PER_BLOCK];
        if (lid == 0) s_final[wid] = v;
        __syncthreads();

        if (t == 0) {
            float total = 0.0f;
            #pragma unroll
            for (int w = 0; w < WARPS_PER_BLOCK; w++) total += s_final[w];
            out[0] = total * (1.0f / (float)N_ROWS);
            g_count = 0;   // reset for next graph replay
        }
    }
}

extern "C" void kernel_launch(void* const* d_in, const int* in_sizes, int n_in,
                              void* d_out, int out_size) {
    const float* A      = (const float*)d_in[0];  // issues_1_geb [8192,1024]
    const float* B      = (const float*)d_in[1];  // issues_2_geb [8192,1024]
    const float* labels = (const float*)d_in[2];  // labels [8192]
    float* out = (float*)d_out;

    fused_cosine_mse_kernel<<<NBLOCKS, THREADS>>>(A, B, labels, out);
}

// round 6
// speedup vs baseline: 1.0029x; 1.0029x over previous
#include <cuda_runtime.h>

#define N_ROWS 8192
#define D_DIM  1024
#define THREADS 256
#define NBLOCKS 1024
#define WARPS_PER_BLOCK (THREADS / 32)                   // 8
#define F4_PER_LANE (D_DIM / 4 / 32)                     // 8
#define PARTIALS_PER_THREAD (NBLOCKS / THREADS)          // 4

__device__ float        g_partial[NBLOCKS];
__device__ unsigned int g_count = 0;

__global__ __launch_bounds__(THREADS, 8)   // regs=32 -> 8 CTAs/SM = 64 warps, single wave
void fused_cosine_mse_kernel(const float* __restrict__ A,
                             const float* __restrict__ B,
                             const float* __restrict__ labels,
                             float* __restrict__ out) {
    const int t   = threadIdx.x;
    const int wid = t >> 5;
    const int lid = t & 31;
    const int row = blockIdx.x * WARPS_PER_BLOCK + wid;   // one row per warp

    const float4* a4 = reinterpret_cast<const float4*>(A + (size_t)row * D_DIM) + lid;
    const float4* b4 = reinterpret_cast<const float4*>(B + (size_t)row * D_DIM) + lid;

    const float label = labels[row];   // overlaps with the streaming loads

    // Front-batch all 16 loads, A/B interleaved (streaming: no reuse, evict-first)
    float4 av[F4_PER_LANE], bv[F4_PER_LANE];
    #pragma unroll
    for (int k = 0; k < F4_PER_LANE; k++) {
        av[k] = __ldcs(a4 + k * 32);
        bv[k] = __ldcs(b4 + k * 32);
    }
    // Scheduling fence: keep compute from being hoisted between the loads
    asm volatile("" ::: "memory");

    float dot = 0.0f, na = 0.0f, nb = 0.0f;
    #pragma unroll
    for (int k = 0; k < F4_PER_LANE; k++) {
        dot += av[k].x * bv[k].x + av[k].y * bv[k].y + av[k].z * bv[k].z + av[k].w * bv[k].w;
        na  += av[k].x * av[k].x + av[k].y * av[k].y + av[k].z * av[k].z + av[k].w * av[k].w;
        nb  += bv[k].x * bv[k].x + bv[k].y * bv[k].y + bv[k].z * bv[k].z + bv[k].w * bv[k].w;
    }

    // Butterfly reduce: every lane ends with full-row sums
    #pragma unroll
    for (int off = 16; off > 0; off >>= 1) {
        dot += __shfl_xor_sync(0xFFFFFFFFu, dot, off);
        na  += __shfl_xor_sync(0xFFFFFFFFu, na,  off);
        nb  += __shfl_xor_sync(0xFFFFFFFFu, nb,  off);
    }

    const float score = dot * rsqrtf(na * nb);
    const float diff  = score - label;
    const float acc   = diff * diff;

    // Block reduction of 8 warp values
    __shared__ float s_warp[WARPS_PER_BLOCK];
    __shared__ bool  s_is_last;
    if (lid == 0) s_warp[wid] = acc;
    __syncthreads();

    if (t == 0) {
        float bsum = 0.0f;
        #pragma unroll
        for (int w = 0; w < WARPS_PER_BLOCK; w++) bsum += s_warp[w];
        g_partial[blockIdx.x] = bsum;
        __threadfence();
        const unsigned int prev = atomicAdd(&g_count, 1u);
        s_is_last = (prev == NBLOCKS - 1);
    }
    __syncthreads();

    if (s_is_last) {
        __threadfence();   // acquire: all g_partial writes visible
        float v = 0.0f;
        #pragma unroll
        for (int i = 0; i < PARTIALS_PER_THREAD; i++)
            v += g_partial[t + i * THREADS];

        #pragma unroll
        for (int off = 16; off > 0; off >>= 1)
            v += __shfl_xor_sync(0xFFFFFFFFu, v, off);

        __shared__ float s_final[WARPS_PER_BLOCK];
        if (lid == 0) s_final[wid] = v;
        __syncthreads();

        if (t == 0) {
            float total = 0.0f;
            #pragma unroll
            for (int w = 0; w < WARPS_PER_BLOCK; w++) total += s_final[w];
            out[0] = total * (1.0f / (float)N_ROWS);
            g_count = 0;   // reset for next graph replay
        }
    }
}

extern "C" void kernel_launch(void* const* d_in, const int* in_sizes, int n_in,
                              void* d_out, int out_size) {
    const float* A      = (const float*)d_in[0];  // issues_1_geb [8192,1024]
    const float* B      = (const float*)d_in[1];  // issues_2_geb [8192,1024]
    const float* labels = (const float*)d_in[2];  // labels [8192]
    float* out = (float*)d_out;

    fused_cosine_mse_kernel<<<NBLOCKS, THREADS>>>(A, B, labels, out);
}